// round 15
// baseline (speedup 1.0000x reference)
#include <cuda_runtime.h>
#include <cstdint>

// out[b,s,d] = x[b,s,d] + enc(s,d); B=8,S=4096,D=1024 fp32. 268 MB traffic.
//
// R15: coarsen BOTH directions. R13 proved 4KB TMA bulk *stores* beat STG
// (35.39us vs 36.0-37.0); R14 proved 8KB chunks / lower concurrency regress.
// This round keeps R13's shape (TPB=256, 4KB chunks, 32KB SMEM, high occ)
// and converts the read path to cp.async.bulk loads too: 8 x 4KB bulk loads
// (mbarrier completion) -> in-place add -> 8 x 4KB bulk stores. The DRAM
// controller sees coarse contiguous transactions in both directions.

#define B_ 8
#define S_ 4096
#define D_ 1024
#define SD4_ ((S_ * D_) / 4)     // 1,048,576 float4 tiles per batch slice
#define TPB 256
#define SLICE_BYTES (TPB * 16)   // 4096 B per batch slice per block
#define TILE_BYTES (B_ * SLICE_BYTES)  // 32768

__global__ __launch_bounds__(TPB) void pe_add_kernel(
    const float4* __restrict__ x, float4* __restrict__ out)
{
    __shared__ __align__(128) float4 stage[B_][TPB];   // 32 KB
    __shared__ __align__(8) unsigned long long mbar;

    const int tid = threadIdx.x;
    const long long blk_off = (long long)blockIdx.x * TPB;

    unsigned int mbar_addr;
    asm("{ .reg .u64 t; cvta.to.shared.u64 t, %1; cvt.u32.u64 %0, t; }"
        : "=r"(mbar_addr) : "l"(&mbar));

    if (tid == 0)
        asm volatile("mbarrier.init.shared.b64 [%0], 1;" :: "r"(mbar_addr) : "memory");
    __syncthreads();

    // Elected thread: expect full tile, issue 8 x 4KB bulk loads.
    if (tid == 0) {
        asm volatile("mbarrier.arrive.expect_tx.shared.b64 _, [%0], %1;"
                     :: "r"(mbar_addr), "r"((unsigned int)TILE_BYTES) : "memory");
#pragma unroll
        for (int b = 0; b < B_; b++) {
            unsigned int saddr;
            asm("{ .reg .u64 t; cvta.to.shared.u64 t, %1; cvt.u32.u64 %0, t; }"
                : "=r"(saddr) : "l"(&stage[b][0]));
            const float4* gsrc = x + (long long)b * SD4_ + blk_off;
            asm volatile(
                "cp.async.bulk.shared::cta.global.mbarrier::complete_tx::bytes "
                "[%0], [%1], %2, [%3];"
                :: "r"(saddr), "l"(gsrc), "r"((unsigned int)SLICE_BYTES),
                   "r"(mbar_addr) : "memory");
        }
    }

    // Encoding computed while the bulk loads are in flight.
    const int idx4 = blockIdx.x * TPB + tid;
    const int d0   = (idx4 & (D_ / 4 - 1)) << 2;
    const float sf = (float)(idx4 >> 8);               // s = idx4 / 256
    const float c  = -(13.287712379549449f / 1024.0f); // -log2(1e4)/D
    const float e0 = sinf(sf * exp2f((float)(d0 + 0) * c));
    const float e1 = cosf(sf * exp2f((float)(d0 + 1) * c));
    const float e2 = sinf(sf * exp2f((float)(d0 + 2) * c));
    const float e3 = cosf(sf * exp2f((float)(d0 + 3) * c));

    // Wait for the tile (parity 0, acquire).
    {
        unsigned int done;
        asm volatile(
            "{\n\t.reg .pred p;\n\t"
            "mbarrier.try_wait.parity.acquire.cta.shared::cta.b64 p, [%1], 0;\n\t"
            "selp.b32 %0, 1, 0, p;\n\t}"
            : "=r"(done) : "r"(mbar_addr) : "memory");
        while (!done) {
            asm volatile(
                "{\n\t.reg .pred p;\n\t"
                "mbarrier.try_wait.parity.acquire.cta.shared::cta.b64 p, [%1], 0, 0x989680;\n\t"
                "selp.b32 %0, 1, 0, p;\n\t}"
                : "=r"(done) : "r"(mbar_addr) : "memory");
        }
    }

    // In-place add.
#pragma unroll
    for (int b = 0; b < B_; b++) {
        float4 r = stage[b][tid];
        r.x += e0; r.y += e1; r.z += e2; r.w += e3;
        stage[b][tid] = r;
    }

    __syncthreads();
    asm volatile("fence.proxy.async.shared::cta;" ::: "memory");

    // Elected thread: 8 x 4KB bulk stores, then hold SMEM until TMA read done.
    if (tid == 0) {
#pragma unroll
        for (int b = 0; b < B_; b++) {
            unsigned int saddr;
            asm("{ .reg .u64 t; cvta.to.shared.u64 t, %1; cvt.u32.u64 %0, t; }"
                : "=r"(saddr) : "l"(&stage[b][0]));
            float4* gdst = out + (long long)b * SD4_ + blk_off;
            asm volatile(
                "cp.async.bulk.global.shared::cta.bulk_group [%0], [%1], %2;"
                :: "l"(gdst), "r"(saddr), "r"((unsigned int)SLICE_BYTES)
                : "memory");
        }
        asm volatile("cp.async.bulk.commit_group;" ::: "memory");
        asm volatile("cp.async.bulk.wait_group.read 0;" ::: "memory");
    }
}

extern "C" void kernel_launch(void* const* d_in, const int* in_sizes, int n_in,
                              void* d_out, int out_size)
{
    const float4* x = (const float4*)d_in[0];
    float4* out = (float4*)d_out;
    pe_add_kernel<<<SD4_ / TPB, TPB>>>(x, out);
}

// round 16
// speedup vs baseline: 1.0077x; 1.0077x over previous
#include <cuda_runtime.h>
#include <cstdint>

// out[b,s,d] = x[b,s,d] + enc(s,d); B=8,S=4096,D=1024 fp32. 268 MB traffic.
//
// FINAL architecture (R13 + cs-load hint): asymmetric memory paths.
//  - READS:  per-thread LDG.128, front-batched MLP=8, warp-asynchronous
//    (latency hidden across warps). R15 proved block-synchronous TMA bulk
//    loads regress (-5%): reads need warp-level MLP, not coarsening.
//  - WRITES: 8 x 4KB cp.async.bulk stores per block from SMEM staging.
//    R13 proved this beats all STG variants (35.4us vs 36.0-37.0us):
//    coarse contiguous write transactions cut DRAM R/W turnaround loss.
//    R14 proved 8KB chunks / 64KB SMEM / lower occupancy regress.
//  - enc(s,d) computed once per (s,d4) and reused across all 8 batch
//    slices; transcendentals hidden under the in-flight loads.

#define B_ 8
#define S_ 4096
#define D_ 1024
#define SD4_ ((S_ * D_) / 4)     // 1,048,576 float4 tiles per batch slice
#define TPB 256
#define SLICE_BYTES (TPB * 16)   // 4096 B contiguous per batch slice per block

__global__ __launch_bounds__(TPB) void pe_add_kernel(
    const float4* __restrict__ x, float4* __restrict__ out)
{
    __shared__ __align__(128) float4 stage[B_][TPB];   // 32 KB

    const int tid   = threadIdx.x;
    const int idx4  = blockIdx.x * TPB + tid;          // [0, SD4_)
    const int d0    = (idx4 & (D_ / 4 - 1)) << 2;
    const float sf  = (float)(idx4 >> 8);              // s = idx4 / 256

    // Front-batch all 8 batch-slice loads (MLP=8), evict-first.
    float4 v[B_];
#pragma unroll
    for (int b = 0; b < B_; b++)
        v[b] = __ldcs(x + (long long)b * SD4_ + idx4);

    // Encoding computed once, hidden under in-flight loads.
    const float c = -(13.287712379549449f / 1024.0f); // -log2(1e4)/D
    const float e0 = sinf(sf * exp2f((float)(d0 + 0) * c));
    const float e1 = cosf(sf * exp2f((float)(d0 + 1) * c));
    const float e2 = sinf(sf * exp2f((float)(d0 + 2) * c));
    const float e3 = cosf(sf * exp2f((float)(d0 + 3) * c));

#pragma unroll
    for (int b = 0; b < B_; b++) {
        float4 r = v[b];
        r.x += e0; r.y += e1; r.z += e2; r.w += e3;
        stage[b][tid] = r;
    }

    __syncthreads();
    // Order generic SMEM writes before async-proxy (TMA) reads of SMEM.
    asm volatile("fence.proxy.async.shared::cta;" ::: "memory");

    // One elected thread issues 8 x 4KB bulk stores (1D, no tensor map).
    if (tid == 0) {
        const long long blk_off = (long long)blockIdx.x * TPB;
#pragma unroll
        for (int b = 0; b < B_; b++) {
            unsigned int saddr;
            asm("{ .reg .u64 t; cvta.to.shared.u64 t, %1; cvt.u32.u64 %0, t; }"
                : "=r"(saddr) : "l"(&stage[b][0]));
            float4* gdst = out + (long long)b * SD4_ + blk_off;
            asm volatile(
                "cp.async.bulk.global.shared::cta.bulk_group [%0], [%1], %2;"
                :: "l"(gdst), "r"(saddr), "r"((unsigned int)SLICE_BYTES)
                : "memory");
        }
        asm volatile("cp.async.bulk.commit_group;" ::: "memory");
        // Block must not exit while TMA still reads its SMEM.
        asm volatile("cp.async.bulk.wait_group.read 0;" ::: "memory");
    }
}

extern "C" void kernel_launch(void* const* d_in, const int* in_sizes, int n_in,
                              void* d_out, int out_size)
{
    const float4* x = (const float4*)d_in[0];
    float4* out = (float4*)d_out;
    pe_add_kernel<<<SD4_ / TPB, TPB>>>(x, out);
}

// round 17
// speedup vs baseline: 1.0537x; 1.0456x over previous
#include <cuda_runtime.h>
#include <cstdint>

// out[b,s,d] = x[b,s,d] + enc(s,d); B=8,S=4096,D=1024 fp32. 268 MB traffic.
//
// R17 = EXACT R13 re-bench (controlled: R16 differed only by __ldcs on the
// read path and measured 36.64us vs R13's 35.39us). This run decides whether
// R13's session-best was real (default LDG + TMA bulk stores) or sample
// noise.
//
// Architecture: asymmetric memory paths.
//  - READS:  per-thread LDG.128 (default policy), front-batched MLP=8,
//    warp-asynchronous. (R15: block-sync TMA bulk loads regress -5%.)
//  - WRITES: 8 x 4KB cp.async.bulk stores per block from 32KB SMEM staging.
//    (R14: 8KB chunks / 64KB SMEM regress; R13: 4KB chunks best.)
//  - enc(s,d) computed once per (s,d4), reused across all 8 batch slices.

#define B_ 8
#define S_ 4096
#define D_ 1024
#define SD4_ ((S_ * D_) / 4)     // 1,048,576 float4 tiles per batch slice
#define TPB 256
#define SLICE_BYTES (TPB * 16)   // 4096 B contiguous per batch slice per block

__global__ __launch_bounds__(TPB) void pe_add_kernel(
    const float4* __restrict__ x, float4* __restrict__ out)
{
    __shared__ __align__(128) float4 stage[B_][TPB];   // 32 KB

    const int tid   = threadIdx.x;
    const int idx4  = blockIdx.x * TPB + tid;          // [0, SD4_)
    const int d0    = (idx4 & (D_ / 4 - 1)) << 2;
    const float sf  = (float)(idx4 >> 8);              // s = idx4 / 256

    // Front-batch all 8 batch-slice loads (MLP=8).
    float4 v[B_];
#pragma unroll
    for (int b = 0; b < B_; b++)
        v[b] = x[(long long)b * SD4_ + idx4];

    // Encoding computed once, hidden under in-flight loads.
    const float c = -(13.287712379549449f / 1024.0f); // -log2(1e4)/D
    const float e0 = sinf(sf * exp2f((float)(d0 + 0) * c));
    const float e1 = cosf(sf * exp2f((float)(d0 + 1) * c));
    const float e2 = sinf(sf * exp2f((float)(d0 + 2) * c));
    const float e3 = cosf(sf * exp2f((float)(d0 + 3) * c));

#pragma unroll
    for (int b = 0; b < B_; b++) {
        float4 r = v[b];
        r.x += e0; r.y += e1; r.z += e2; r.w += e3;
        stage[b][tid] = r;
    }

    __syncthreads();
    // Order generic SMEM writes before async-proxy (TMA) reads of SMEM.
    asm volatile("fence.proxy.async.shared::cta;" ::: "memory");

    // One elected thread issues 8 x 4KB bulk stores (1D, no tensor map).
    if (tid == 0) {
        const long long blk_off = (long long)blockIdx.x * TPB;
#pragma unroll
        for (int b = 0; b < B_; b++) {
            unsigned int saddr;
            asm("{ .reg .u64 t; cvta.to.shared.u64 t, %1; cvt.u32.u64 %0, t; }"
                : "=r"(saddr) : "l"(&stage[b][0]));
            float4* gdst = out + (long long)b * SD4_ + blk_off;
            asm volatile(
                "cp.async.bulk.global.shared::cta.bulk_group [%0], [%1], %2;"
                :: "l"(gdst), "r"(saddr), "r"((unsigned int)SLICE_BYTES)
                : "memory");
        }
        asm volatile("cp.async.bulk.commit_group;" ::: "memory");
        // Block must not exit while TMA still reads its SMEM.
        asm volatile("cp.async.bulk.wait_group.read 0;" ::: "memory");
    }
}

extern "C" void kernel_launch(void* const* d_in, const int* in_sizes, int n_in,
                              void* d_out, int out_size)
{
    const float4* x = (const float4*)d_in[0];
    float4* out = (float4*)d_out;
    pe_add_kernel<<<SD4_ / TPB, TPB>>>(x, out);
}